// round 1
// baseline (speedup 1.0000x reference)
#include <cuda_runtime.h>
#include <cuda_bf16.h>

// Problem constants
#define BATCH   8
#define SEQ     2048
#define EMBED   1024
#define HEAD    128
#define MROWS   (BATCH * SEQ)      // 16384

// Scratch for K and V projections (8 MB each) — __device__ globals, no alloc.
__device__ float g_Kbuf[MROWS * HEAD];
__device__ float g_Vbuf[MROWS * HEAD];

// ---------------------------------------------------------------------------
// Projection GEMM: computes K = x @ Wk and V = x @ Wv in one kernel.
// Logical combined N = 256 (Wk cols 0..127 -> Kbuf, Wv cols -> Vbuf).
// Tiles: BM=64, BN=64, BK=16. 256 threads, 4x4 register tile per thread.
// grid = (MROWS/64, 4)
// ---------------------------------------------------------------------------
__global__ __launch_bounds__(256) void proj_kernel(
    const float* __restrict__ x,
    const float* __restrict__ Wk,
    const float* __restrict__ Wv)
{
    const int bm = blockIdx.x;       // 0..255
    const int bn = blockIdx.y;       // 0..3

    __shared__ float As[16][64];     // [k][m]  (A transposed)
    __shared__ float Bs[16][64];     // [k][n]

    const int tid = threadIdx.x;
    const int tx = tid & 15;         // 0..15 (n direction)
    const int ty = tid >> 4;         // 0..15 (m direction)

    const float* W = (bn < 2) ? Wk : Wv;
    const int ncol0 = (bn & 1) * 64;

    // A load mapping: each thread one float4 along K
    const int a_m  = tid >> 2;            // 0..63
    const int a_k4 = (tid & 3) * 4;       // 0,4,8,12
    // B load mapping: each thread one float4 along N
    const int b_k  = tid >> 4;            // 0..15
    const int b_n4 = (tid & 15) * 4;      // 0..60

    float acc[4][4] = {};

    const float* xrow = x + (bm * 64 + a_m) * EMBED;

    for (int k0 = 0; k0 < EMBED; k0 += 16) {
        float4 av = *(const float4*)&xrow[k0 + a_k4];
        As[a_k4 + 0][a_m] = av.x;
        As[a_k4 + 1][a_m] = av.y;
        As[a_k4 + 2][a_m] = av.z;
        As[a_k4 + 3][a_m] = av.w;
        float4 bv = *(const float4*)&W[(k0 + b_k) * HEAD + ncol0 + b_n4];
        *(float4*)&Bs[b_k][b_n4] = bv;
        __syncthreads();

        #pragma unroll
        for (int kk = 0; kk < 16; kk++) {
            float a[4], b[4];
            #pragma unroll
            for (int i = 0; i < 4; i++) a[i] = As[kk][ty * 4 + i];
            #pragma unroll
            for (int j = 0; j < 4; j++) b[j] = Bs[kk][tx * 4 + j];
            #pragma unroll
            for (int i = 0; i < 4; i++)
                #pragma unroll
                for (int j = 0; j < 4; j++)
                    acc[i][j] += a[i] * b[j];
        }
        __syncthreads();
    }

    float* dst = (bn < 2) ? g_Kbuf : g_Vbuf;
    #pragma unroll
    for (int i = 0; i < 4; i++) {
        float4 v = make_float4(acc[i][0], acc[i][1], acc[i][2], acc[i][3]);
        *(float4*)&dst[(bm * 64 + ty * 4 + i) * HEAD + ncol0 + tx * 4] = v;
    }
}

// ---------------------------------------------------------------------------
// Flash attention (causal), fp32. Q = K (reference bug preserved).
// One CTA handles a 64-query tile; streams 64-key tiles with online softmax.
// grid = (SEQ/64, BATCH), 256 threads, dynamic smem.
// ---------------------------------------------------------------------------
#define BQ 64
#define BK 64

__global__ __launch_bounds__(256) void attn_kernel(float* __restrict__ out)
{
    // Reverse qi so the heaviest (largest-i) causal tiles are scheduled first.
    const int qi = (int)gridDim.x - 1 - (int)blockIdx.x;
    const int b  = blockIdx.y;

    extern __shared__ float sm[];
    float* Qt   = sm;                     // [128][65]  transposed Q tile
    float* Kt   = Qt + 128 * 65;          // [128][65]  transposed K tile
    float* Vs   = Kt + 128 * 65;          // [64][132]  V tile, row-major padded
    float* Ss   = Vs + 64 * 132;          // [64][65]   scores / probs
    float* mrow = Ss + 64 * 65;           // [64]
    float* lrow = mrow + 64;              // [64]
    float* srow = lrow + 64;              // [64]

    const int tid = threadIdx.x;
    const float* Kbase = g_Kbuf + (size_t)b * SEQ * HEAD;
    const float* Vbase = g_Vbuf + (size_t)b * SEQ * HEAD;

    // --- load Q tile (from Kbuf: q = key(x)) transposed into Qt ---
    {
        const int row = tid >> 2;
        const int d4  = (tid & 3) * 4;
        const float* src = &Kbase[(qi * BQ + row) * HEAD];
        #pragma unroll
        for (int it = 0; it < 8; it++) {
            int d = d4 + it * 16;
            float4 v = *(const float4*)&src[d];
            Qt[(d + 0) * 65 + row] = v.x;
            Qt[(d + 1) * 65 + row] = v.y;
            Qt[(d + 2) * 65 + row] = v.z;
            Qt[(d + 3) * 65 + row] = v.w;
        }
    }
    if (tid < 64) { mrow[tid] = -1e30f; lrow[tid] = 0.0f; }

    // Output accumulator: thread owns row (tid>>2), cols (tid&3)*4 + 16*jj (+u)
    float O[32] = {};
    const int orow = tid >> 2;
    const int oc4  = (tid & 3) * 4;

    const int tx = tid & 15;   // S tile: cols tx*4..+3
    const int ty = tid >> 4;   // S tile: rows ty*4..+3
    const float sc = 0.08838834764831845f;  // 1/sqrt(128)

    __syncthreads();

    for (int j = 0; j <= qi; j++) {
        // --- load K,V tiles ---
        {
            const int row = tid >> 2;
            const int d4  = (tid & 3) * 4;
            const float* ksrc = &Kbase[(j * BK + row) * HEAD];
            const float* vsrc = &Vbase[(j * BK + row) * HEAD];
            #pragma unroll
            for (int it = 0; it < 8; it++) {
                int d = d4 + it * 16;
                float4 kv = *(const float4*)&ksrc[d];
                Kt[(d + 0) * 65 + row] = kv.x;
                Kt[(d + 1) * 65 + row] = kv.y;
                Kt[(d + 2) * 65 + row] = kv.z;
                Kt[(d + 3) * 65 + row] = kv.w;
                float4 vv = *(const float4*)&vsrc[d];
                *(float4*)&Vs[row * 132 + d] = vv;
            }
        }
        __syncthreads();

        // --- S = Q K^T (4x4 per thread over the 64x64 tile) ---
        float sacc[4][4] = {};
        #pragma unroll 4
        for (int d = 0; d < 128; d++) {
            float a[4], bb[4];
            #pragma unroll
            for (int i = 0; i < 4; i++) a[i] = Qt[d * 65 + ty * 4 + i];
            #pragma unroll
            for (int jj = 0; jj < 4; jj++) bb[jj] = Kt[d * 65 + tx * 4 + jj];
            #pragma unroll
            for (int i = 0; i < 4; i++)
                #pragma unroll
                for (int jj = 0; jj < 4; jj++)
                    sacc[i][jj] += a[i] * bb[jj];
        }
        const bool diag = (j == qi);
        #pragma unroll
        for (int i = 0; i < 4; i++) {
            int r = ty * 4 + i;
            #pragma unroll
            for (int jj = 0; jj < 4; jj++) {
                int kc = tx * 4 + jj;
                float v = sacc[i][jj] * sc;
                if (diag && kc > r) v = -1e30f;
                Ss[r * 65 + kc] = v;
            }
        }
        __syncthreads();

        // --- online softmax row update (64 threads) ---
        if (tid < 64) {
            const int r = tid;
            float m_old = mrow[r];
            float mx = m_old;
            #pragma unroll 8
            for (int k = 0; k < 64; k++) mx = fmaxf(mx, Ss[r * 65 + k]);
            float scale = __expf(m_old - mx);
            float sum = 0.0f;
            #pragma unroll 8
            for (int k = 0; k < 64; k++) {
                float p = __expf(Ss[r * 65 + k] - mx);
                Ss[r * 65 + k] = p;
                sum += p;
            }
            mrow[r] = mx;
            lrow[r] = lrow[r] * scale + sum;
            srow[r] = scale;
        }
        __syncthreads();

        // --- O = O*scale + P @ V ---
        {
            const float scale = srow[orow];
            #pragma unroll
            for (int u = 0; u < 32; u++) O[u] *= scale;
            const float* Prow = &Ss[orow * 65];
            #pragma unroll 2
            for (int k = 0; k < 64; k++) {
                const float p = Prow[k];
                const float* vr = &Vs[k * 132];
                #pragma unroll
                for (int jj = 0; jj < 8; jj++) {
                    float4 v = *(const float4*)&vr[oc4 + 16 * jj];
                    O[jj * 4 + 0] += p * v.x;
                    O[jj * 4 + 1] += p * v.y;
                    O[jj * 4 + 2] += p * v.z;
                    O[jj * 4 + 3] += p * v.w;
                }
            }
        }
        __syncthreads();
    }

    // --- finalize: divide by l, write out ---
    const float inv_l = 1.0f / lrow[orow];
    float* orow_ptr = out + ((size_t)b * SEQ + qi * BQ + orow) * HEAD;
    #pragma unroll
    for (int jj = 0; jj < 8; jj++) {
        float4 v = make_float4(O[jj * 4 + 0] * inv_l, O[jj * 4 + 1] * inv_l,
                               O[jj * 4 + 2] * inv_l, O[jj * 4 + 3] * inv_l);
        *(float4*)&orow_ptr[oc4 + 16 * jj] = v;
    }
}

// ---------------------------------------------------------------------------
// Launch
// ---------------------------------------------------------------------------
extern "C" void kernel_launch(void* const* d_in, const int* in_sizes, int n_in,
                              void* d_out, int out_size)
{
    const float* x  = (const float*)d_in[0];
    const float* Wk = (const float*)d_in[1];
    // d_in[2] = W_query: unused (reference uses key() for q too)
    const float* Wv = (const float*)d_in[3];
    float* out = (float*)d_out;

    // Projection: grid (16384/64, 4)
    dim3 pgrid(MROWS / 64, 4);
    proj_kernel<<<pgrid, 256>>>(x, Wk, Wv);

    // Attention: dynamic smem
    const int smem_bytes = (128 * 65 * 2 + 64 * 132 + 64 * 65 + 3 * 64) * (int)sizeof(float);
    static bool attr_set_dummy = []() {
        return true;
    }();
    (void)attr_set_dummy;
    cudaFuncSetAttribute(attn_kernel, cudaFuncAttributeMaxDynamicSharedMemorySize, smem_bytes);

    dim3 agrid(SEQ / BQ, BATCH);
    attn_kernel<<<agrid, 256, smem_bytes>>>(out);
}